// round 1
// baseline (speedup 1.0000x reference)
#include <cuda_runtime.h>
#include <math.h>

// ---------------- problem constants ----------------
#define NB   16      // batch
#define CDIM 256     // dim
#define HH   64
#define WW   64
#define NPIX 4096    // H*W
#define NHKD 128     // key_dim*heads
#define DH   256     // 2*key_dim*heads
#define CQKV 512     // 2*dh
#define HEADS 8
#define KD    16
#define DHEAD 32
#define POS   16

// ---------------- device scratch (static, no allocs) ----------------
__device__ float d_y[NB * CQKV * NPIX];        // qkv projections (B,512,4096)
__device__ float d_gate[NB * CDIM * NPIX];     // gate branch output
__device__ float d_rowmean[NB * CQKV * HH];    // mean over W
__device__ float d_colmean[NB * CQKV * WW];    // mean over H
__device__ float d_attR[NB * DH * HH];         // relu'd row attention out (dh, H)
__device__ float d_attC[NB * DH * WW];
__device__ float d_xr[NB * DH * HH];           // after Wr conv
__device__ float d_xc[NB * DH * WW];

__device__ float g_Wall[CQKV * CDIM];          // folded [Wq;Wk;Wv]
__device__ float g_Wpw[CDIM * CQKV];
__device__ float g_Wp[CDIM * DH];
__device__ float g_Wr[DH * DH];
__device__ float g_Wc[DH * DH];
__device__ float g_gdw[CQKV];                  // wdw*sdw
__device__ float g_pe[4 * NHKD * 64];          // interpolated pe: rq, rk, cq, ck

// ---------------- prep: fold scales, interpolate pe ----------------
__global__ void k_prep(const float* __restrict__ Wq, const float* __restrict__ sq,
                       const float* __restrict__ Wk, const float* __restrict__ sk,
                       const float* __restrict__ Wv, const float* __restrict__ sv,
                       const float* __restrict__ Wpw, const float* __restrict__ spw,
                       const float* __restrict__ Wp, const float* __restrict__ sp,
                       const float* __restrict__ Wr, const float* __restrict__ sr,
                       const float* __restrict__ Wc, const float* __restrict__ sc,
                       const float* __restrict__ wdw, const float* __restrict__ sdw,
                       const float* __restrict__ pe_rq, const float* __restrict__ pe_rk,
                       const float* __restrict__ pe_cq, const float* __restrict__ pe_ck)
{
    int tid = blockIdx.x * blockDim.x + threadIdx.x;   // 131072 total
    if (tid < CQKV * CDIM) {
        int o = tid >> 8, c = tid & 255;
        float wv;
        if (o < 128)      wv = sq[o]       * Wq[o * 256 + c];
        else if (o < 256) wv = sk[o - 128] * Wk[(o - 128) * 256 + c];
        else              wv = sv[o - 256] * Wv[(o - 256) * 256 + c];
        g_Wall[tid] = wv;
        g_Wpw[tid] = spw[tid >> 9] * Wpw[tid];         // 256x512 = same count
    }
    if (tid < CDIM * DH) {
        int o = tid >> 8;
        g_Wp[tid] = sp[o] * Wp[tid];
        g_Wr[tid] = sr[o] * Wr[tid];
        g_Wc[tid] = sc[o] * Wc[tid];
    }
    if (tid < CQKV) g_gdw[tid] = wdw[tid] * sdw[tid];
    if (tid < 4 * NHKD * 64) {
        int e = tid >> 13, rem = tid & 8191;
        int c = rem >> 6, i = rem & 63;
        float pos = (i + 0.5f) * 0.25f - 0.5f;
        pos = fminf(fmaxf(pos, 0.f), 15.f);
        int i0 = (int)pos;
        int i1 = min(i0 + 1, 15);
        float w = pos - (float)i0;
        const float* src = (e == 0) ? pe_rq : (e == 1) ? pe_rk : (e == 2) ? pe_cq : pe_ck;
        g_pe[tid] = src[c * POS + i0] * (1.f - w) + src[c * POS + i1] * w;
    }
}

// ---------------- tiled SGEMM common config ----------------
#define TM 128
#define TN 128
#define TK 16

// GEMM 1: y[b] (512 x 4096) = Wall @ x[b] + bias
__global__ void __launch_bounds__(256, 2)
k_gemm_qkv(const float* __restrict__ X,
           const float* __restrict__ bq, const float* __restrict__ bkk,
           const float* __restrict__ bvv)
{
    int b  = blockIdx.z;
    int m0 = blockIdx.y * TM;
    int n0 = blockIdx.x * TN;
    __shared__ float As[TK][TM];
    __shared__ float Bs[TK][TN];
    int t  = threadIdx.x;
    int ty = t >> 4, tx = t & 15;
    int ry = ty * 8, cx = tx * 8;
    float acc[8][8];
#pragma unroll
    for (int i = 0; i < 8; i++)
#pragma unroll
        for (int j = 0; j < 8; j++) acc[i][j] = 0.f;

    const float* Xb = X + b * (CDIM * NPIX);
    for (int k0 = 0; k0 < CDIM; k0 += TK) {
#pragma unroll
        for (int l = 0; l < 2; l++) {
            int v = t + l * 256;
            int am = v >> 2, ak = (v & 3) * 4;
            float4 a4 = *(const float4*)(g_Wall + (m0 + am) * CDIM + k0 + ak);
            As[ak + 0][am] = a4.x; As[ak + 1][am] = a4.y;
            As[ak + 2][am] = a4.z; As[ak + 3][am] = a4.w;
            int bkr = v >> 5, bnc = (v & 31) * 4;
            *(float4*)&Bs[bkr][bnc] = *(const float4*)(Xb + (k0 + bkr) * NPIX + n0 + bnc);
        }
        __syncthreads();
#pragma unroll
        for (int kk = 0; kk < TK; kk++) {
            float ar[8], br[8];
            *(float4*)(ar)     = *(const float4*)&As[kk][ry];
            *(float4*)(ar + 4) = *(const float4*)&As[kk][ry + 4];
            *(float4*)(br)     = *(const float4*)&Bs[kk][cx];
            *(float4*)(br + 4) = *(const float4*)&Bs[kk][cx + 4];
#pragma unroll
            for (int i = 0; i < 8; i++)
#pragma unroll
                for (int j = 0; j < 8; j++) acc[i][j] += ar[i] * br[j];
        }
        __syncthreads();
    }
#pragma unroll
    for (int i = 0; i < 8; i++) {
        int oc = m0 + ry + i;
        float bias = (oc < 128) ? bq[oc] : (oc < 256) ? bkk[oc - 128] : bvv[oc - 256];
        float* orow = d_y + (b * CQKV + oc) * NPIX + n0 + cx;
#pragma unroll
        for (int j = 0; j < 8; j++) orow[j] = acc[i][j] + bias;
    }
}

// means over W (rowmean) and H (colmean) of y
__global__ void k_means()
{
    int c = blockIdx.x, b = blockIdx.y;
    __shared__ float buf[64][65];
    const float* row = d_y + (b * CQKV + c) * NPIX;
    int t = threadIdx.x;
#pragma unroll
    for (int l = 0; l < 16; l++) {
        int p = t + l * 256;
        buf[p >> 6][p & 63] = row[p];
    }
    __syncthreads();
    if (t < 64) {
        float s = 0.f;
#pragma unroll
        for (int w = 0; w < 64; w++) s += buf[t][w];
        d_rowmean[(b * CQKV + c) * 64 + t] = s * (1.f / 64.f);
    } else if (t < 128) {
        int w = t - 64;
        float s = 0.f;
#pragma unroll
        for (int h = 0; h < 64; h++) s += buf[h][w];
        d_colmean[(b * CQKV + c) * 64 + w] = s * (1.f / 64.f);
    }
}

// tiny axial attention: one block per (head, batch, dir); 64 threads (one per position)
__global__ void k_attn()
{
    int head = blockIdx.x, b = blockIdx.y, dir = blockIdx.z;
    const float* mean = dir ? d_colmean : d_rowmean;
    const float* peq  = g_pe + (dir ? 2 : 0) * (NHKD * 64);
    const float* pek  = g_pe + (dir ? 3 : 1) * (NHKD * 64);
    float* outp = dir ? d_attC : d_attR;
    __shared__ float km[KD][64];
    __shared__ float vm[DHEAD][64];
    int t = threadIdx.x;  // 0..63
#pragma unroll
    for (int l = 0; l < KD; l++) {
        int idx = t + l * 64;
        int kd = idx >> 6, i = idx & 63;
        int c = head * KD + kd;
        km[kd][i] = mean[(b * CQKV + c) * 64 + i] + pek[c * 64 + i];
    }
#pragma unroll
    for (int l = 0; l < DHEAD; l++) {
        int idx = t + l * 64;
        int d = idx >> 6, i = idx & 63;
        int c = DH + head * DHEAD + d;   // v starts at channel 256
        vm[d][i] = mean[(b * CQKV + c) * 64 + i];
    }
    float qreg[KD];
#pragma unroll
    for (int kd = 0; kd < KD; kd++) {
        int c = head * KD + kd;
        qreg[kd] = mean[(b * CQKV + c) * 64 + t] + peq[c * 64 + t];
    }
    __syncthreads();
    float lg[64];
    float mx = -1e30f;
#pragma unroll
    for (int j = 0; j < 64; j++) {
        float s = 0.f;
#pragma unroll
        for (int kd = 0; kd < KD; kd++) s += qreg[kd] * km[kd][j];
        s *= 0.25f;   // KEY_DIM^-0.5
        lg[j] = s;
        mx = fmaxf(mx, s);
    }
    float sum = 0.f;
#pragma unroll
    for (int j = 0; j < 64; j++) {
        float e = __expf(lg[j] - mx);
        lg[j] = e;
        sum += e;
    }
    float inv = 1.f / sum;
    for (int d = 0; d < DHEAD; d++) {
        float o = 0.f;
#pragma unroll
        for (int j = 0; j < 64; j++) o += lg[j] * vm[d][j];
        o *= inv;
        outp[(b * DH + head * DHEAD + d) * 64 + t] = fmaxf(o, 0.f);   // relu before conv
    }
}

// xr = Wr' @ attR + br ; xc = Wc' @ attC + bc   (tiny: 256x64 per batch-dir)
__global__ void k_xconv(const float* __restrict__ br, const float* __restrict__ bc)
{
    int dir = blockIdx.z, b = blockIdx.y;
    int idx = blockIdx.x * 256 + threadIdx.x;  // 0..16383
    int oc = idx >> 6, pos = idx & 63;
    const float* W = dir ? g_Wc : g_Wr;
    const float* a = (dir ? d_attC : d_attR) + b * DH * 64;
    float acc = 0.f;
#pragma unroll 8
    for (int k = 0; k < DH; k++) acc += W[oc * DH + k] * a[k * 64 + pos];
    float bias = dir ? bc[oc] : br[oc];
    float* o = (dir ? d_xc : d_xr);
    o[(b * DH + oc) * 64 + pos] = acc + bias;
}

// GEMM 2: gate[b] (256 x 4096) = Wpw' @ relu(gdw*y + bdw) + bpw
__global__ void __launch_bounds__(256, 2)
k_gate(const float* __restrict__ bdw, const float* __restrict__ bpw)
{
    int b  = blockIdx.z;
    int m0 = blockIdx.y * TM;
    int n0 = blockIdx.x * TN;
    __shared__ float As[TK][TM];
    __shared__ float Bs[TK][TN];
    int t  = threadIdx.x;
    int ty = t >> 4, tx = t & 15;
    int ry = ty * 8, cx = tx * 8;
    float acc[8][8];
#pragma unroll
    for (int i = 0; i < 8; i++)
#pragma unroll
        for (int j = 0; j < 8; j++) acc[i][j] = 0.f;

    for (int k0 = 0; k0 < CQKV; k0 += TK) {
#pragma unroll
        for (int l = 0; l < 2; l++) {
            int v = t + l * 256;
            int am = v >> 2, ak = (v & 3) * 4;
            float4 a4 = *(const float4*)(g_Wpw + (m0 + am) * CQKV + k0 + ak);
            As[ak + 0][am] = a4.x; As[ak + 1][am] = a4.y;
            As[ak + 2][am] = a4.z; As[ak + 3][am] = a4.w;
            int bkr = v >> 5, bnc = (v & 31) * 4;
            int c = k0 + bkr;
            float g = g_gdw[c], bb = bdw[c];
            float4 yv = *(const float4*)(d_y + (b * CQKV + c) * NPIX + n0 + bnc);
            yv.x = fmaxf(fmaf(yv.x, g, bb), 0.f);
            yv.y = fmaxf(fmaf(yv.y, g, bb), 0.f);
            yv.z = fmaxf(fmaf(yv.z, g, bb), 0.f);
            yv.w = fmaxf(fmaf(yv.w, g, bb), 0.f);
            *(float4*)&Bs[bkr][bnc] = yv;
        }
        __syncthreads();
#pragma unroll
        for (int kk = 0; kk < TK; kk++) {
            float ar[8], br[8];
            *(float4*)(ar)     = *(const float4*)&As[kk][ry];
            *(float4*)(ar + 4) = *(const float4*)&As[kk][ry + 4];
            *(float4*)(br)     = *(const float4*)&Bs[kk][cx];
            *(float4*)(br + 4) = *(const float4*)&Bs[kk][cx + 4];
#pragma unroll
            for (int i = 0; i < 8; i++)
#pragma unroll
                for (int j = 0; j < 8; j++) acc[i][j] += ar[i] * br[j];
        }
        __syncthreads();
    }
#pragma unroll
    for (int i = 0; i < 8; i++) {
        int oc = m0 + ry + i;
        float bias = bpw[oc];
        float* orow = d_gate + (b * CDIM + oc) * NPIX + n0 + cx;
#pragma unroll
        for (int j = 0; j < 8; j++) orow[j] = acc[i][j] + bias;
    }
}

// GEMM 3 + epilogue: out = hsig(Wp' @ relu(v + xr + xc) + bp) * gate
__global__ void __launch_bounds__(256, 2)
k_final(const float* __restrict__ bp, float* __restrict__ out)
{
    int b  = blockIdx.z;
    int m0 = blockIdx.y * TM;
    int n0 = blockIdx.x * TN;
    __shared__ float As[TK][TM];
    __shared__ float Bs[TK][TN];
    int t  = threadIdx.x;
    int ty = t >> 4, tx = t & 15;
    int ry = ty * 8, cx = tx * 8;
    float acc[8][8];
#pragma unroll
    for (int i = 0; i < 8; i++)
#pragma unroll
        for (int j = 0; j < 8; j++) acc[i][j] = 0.f;

    for (int k0 = 0; k0 < DH; k0 += TK) {
#pragma unroll
        for (int l = 0; l < 2; l++) {
            int v = t + l * 256;
            int am = v >> 2, ak = (v & 3) * 4;
            float4 a4 = *(const float4*)(g_Wp + (m0 + am) * DH + k0 + ak);
            As[ak + 0][am] = a4.x; As[ak + 1][am] = a4.y;
            As[ak + 2][am] = a4.z; As[ak + 3][am] = a4.w;
            int bkr = v >> 5, bnc = (v & 31) * 4;
            int c = k0 + bkr;
            int p = n0 + bnc;
            int h = p >> 6, wb = p & 63;
            float4 yv = *(const float4*)(d_y + (b * CQKV + DH + c) * NPIX + p);
            float xrv = d_xr[(b * DH + c) * 64 + h];
            const float* xcr = d_xc + (b * DH + c) * 64;
            yv.x = fmaxf(yv.x + xrv + xcr[wb + 0], 0.f);
            yv.y = fmaxf(yv.y + xrv + xcr[wb + 1], 0.f);
            yv.z = fmaxf(yv.z + xrv + xcr[wb + 2], 0.f);
            yv.w = fmaxf(yv.w + xrv + xcr[wb + 3], 0.f);
            *(float4*)&Bs[bkr][bnc] = yv;
        }
        __syncthreads();
#pragma unroll
        for (int kk = 0; kk < TK; kk++) {
            float ar[8], br[8];
            *(float4*)(ar)     = *(const float4*)&As[kk][ry];
            *(float4*)(ar + 4) = *(const float4*)&As[kk][ry + 4];
            *(float4*)(br)     = *(const float4*)&Bs[kk][cx];
            *(float4*)(br + 4) = *(const float4*)&Bs[kk][cx + 4];
#pragma unroll
            for (int i = 0; i < 8; i++)
#pragma unroll
                for (int j = 0; j < 8; j++) acc[i][j] += ar[i] * br[j];
        }
        __syncthreads();
    }
#pragma unroll
    for (int i = 0; i < 8; i++) {
        int oc = m0 + ry + i;
        float bias = bp[oc];
        const float* grow = d_gate + (b * CDIM + oc) * NPIX + n0 + cx;
        float* orow = out + (b * CDIM + oc) * NPIX + n0 + cx;
#pragma unroll
        for (int j = 0; j < 8; j++) {
            float tt = acc[i][j] + bias;
            float hs = fminf(fmaxf(tt + 3.f, 0.f), 6.f) * (1.f / 6.f);
            orow[j] = hs * grow[j];
        }
    }
}

// ---------------- launch ----------------
extern "C" void kernel_launch(void* const* d_in, const int* in_sizes, int n_in,
                              void* d_out, int out_size)
{
    const float* x     = (const float*)d_in[0];
    const float* Wq    = (const float*)d_in[1];
    const float* sq    = (const float*)d_in[2];
    const float* bq    = (const float*)d_in[3];
    const float* Wk    = (const float*)d_in[4];
    const float* sk    = (const float*)d_in[5];
    const float* bk    = (const float*)d_in[6];
    const float* Wv    = (const float*)d_in[7];
    const float* sv    = (const float*)d_in[8];
    const float* bv    = (const float*)d_in[9];
    const float* pe_rq = (const float*)d_in[10];
    const float* pe_rk = (const float*)d_in[11];
    const float* pe_cq = (const float*)d_in[12];
    const float* pe_ck = (const float*)d_in[13];
    const float* wdw   = (const float*)d_in[14];
    const float* sdw   = (const float*)d_in[15];
    const float* bdw   = (const float*)d_in[16];
    const float* Wpw   = (const float*)d_in[17];
    const float* spw   = (const float*)d_in[18];
    const float* bpw   = (const float*)d_in[19];
    const float* Wr    = (const float*)d_in[20];
    const float* sr    = (const float*)d_in[21];
    const float* br    = (const float*)d_in[22];
    const float* Wc    = (const float*)d_in[23];
    const float* sc    = (const float*)d_in[24];
    const float* bc    = (const float*)d_in[25];
    const float* Wp    = (const float*)d_in[26];
    const float* sp    = (const float*)d_in[27];
    const float* bp    = (const float*)d_in[28];
    float* out = (float*)d_out;

    k_prep<<<512, 256>>>(Wq, sq, Wk, sk, Wv, sv, Wpw, spw, Wp, sp,
                         Wr, sr, Wc, sc, wdw, sdw, pe_rq, pe_rk, pe_cq, pe_ck);
    k_gemm_qkv<<<dim3(NPIX / TN, CQKV / TM, NB), 256>>>(x, bq, bk, bv);
    k_means<<<dim3(CQKV, NB), 256>>>();
    k_attn<<<dim3(HEADS, NB, 2), 64>>>();
    k_xconv<<<dim3(64, NB, 2), 256>>>(br, bc);
    k_gate<<<dim3(NPIX / TN, CDIM / TM, NB), 256>>>(bdw, bpw);
    k_final<<<dim3(NPIX / TN, CDIM / TM, NB), 256>>>(bp, out);
}

// round 3
// speedup vs baseline: 1.0657x; 1.0657x over previous
#include <cuda_runtime.h>
#include <math.h>

// ---------------- problem constants ----------------
#define NB   16      // batch
#define CDIM 256     // dim
#define HH   64
#define WW   64
#define NPIX 4096    // H*W
#define NHKD 128     // key_dim*heads
#define DH   256     // 2*key_dim*heads
#define CQKV 512     // 2*dh
#define HEADS 8
#define KD    16
#define DHEAD 32
#define POS   16

// ---------------- device scratch (static, no allocs) ----------------
__device__ float d_y[NB * CQKV * NPIX];        // qkv projections (B,512,4096)
__device__ float d_gate[NB * CDIM * NPIX];     // gate branch output
__device__ float d_rowmean[NB * CQKV * HH];    // mean over W
__device__ float d_colmean[NB * CQKV * WW];    // mean over H
__device__ float d_attR[NB * DH * HH];         // relu'd row attention out (dh, H)
__device__ float d_attC[NB * DH * WW];
__device__ float d_xr[NB * DH * HH];           // after Wr conv
__device__ float d_xc[NB * DH * WW];

__device__ float g_Wall[CQKV * CDIM];          // folded [Wq;Wk;Wv]
__device__ float g_Wpw[CDIM * CQKV];
__device__ float g_Wp[CDIM * DH];
__device__ float g_Wr[DH * DH];
__device__ float g_Wc[DH * DH];
__device__ float g_gdw[CQKV];                  // wdw*sdw
__device__ float g_pe[4 * NHKD * 64];          // interpolated pe: rq, rk, cq, ck

// ---------------- packed f32x2 helpers ----------------
__device__ __forceinline__ void ffma2(unsigned long long& acc,
                                      unsigned long long a,
                                      unsigned long long b)
{
    asm("fma.rn.f32x2 %0, %1, %2, %0;" : "+l"(acc) : "l"(a), "l"(b));
}
__device__ __forceinline__ unsigned long long dup2(float x)
{
    unsigned long long r;
    asm("mov.b64 %0, {%1, %1};" : "=l"(r) : "f"(x));
    return r;
}
__device__ __forceinline__ float2 unpk(unsigned long long v)
{
    float2 r;
    asm("mov.b64 {%0, %1}, %2;" : "=f"(r.x), "=f"(r.y) : "l"(v));
    return r;
}

// ---------------- prep: fold scales, interpolate pe ----------------
__global__ void k_prep(const float* __restrict__ Wq, const float* __restrict__ sq,
                       const float* __restrict__ Wk, const float* __restrict__ sk,
                       const float* __restrict__ Wv, const float* __restrict__ sv,
                       const float* __restrict__ Wpw, const float* __restrict__ spw,
                       const float* __restrict__ Wp, const float* __restrict__ sp,
                       const float* __restrict__ Wr, const float* __restrict__ sr,
                       const float* __restrict__ Wc, const float* __restrict__ sc,
                       const float* __restrict__ wdw, const float* __restrict__ sdw,
                       const float* __restrict__ pe_rq, const float* __restrict__ pe_rk,
                       const float* __restrict__ pe_cq, const float* __restrict__ pe_ck)
{
    int tid = blockIdx.x * blockDim.x + threadIdx.x;   // 131072 total
    if (tid < CQKV * CDIM) {
        int o = tid >> 8, c = tid & 255;
        float wv;
        if (o < 128)      wv = sq[o]       * Wq[o * 256 + c];
        else if (o < 256) wv = sk[o - 128] * Wk[(o - 128) * 256 + c];
        else              wv = sv[o - 256] * Wv[(o - 256) * 256 + c];
        g_Wall[tid] = wv;
        g_Wpw[tid] = spw[tid >> 9] * Wpw[tid];         // 256x512 = same count
    }
    if (tid < CDIM * DH) {
        int o = tid >> 8;
        g_Wp[tid] = sp[o] * Wp[tid];
        g_Wr[tid] = sr[o] * Wr[tid];
        g_Wc[tid] = sc[o] * Wc[tid];
    }
    if (tid < CQKV) g_gdw[tid] = wdw[tid] * sdw[tid];
    if (tid < 4 * NHKD * 64) {
        int e = tid >> 13, rem = tid & 8191;
        int c = rem >> 6, i = rem & 63;
        float pos = (i + 0.5f) * 0.25f - 0.5f;
        pos = fminf(fmaxf(pos, 0.f), 15.f);
        int i0 = (int)pos;
        int i1 = min(i0 + 1, 15);
        float w = pos - (float)i0;
        const float* src = (e == 0) ? pe_rq : (e == 1) ? pe_rk : (e == 2) ? pe_cq : pe_ck;
        g_pe[tid] = src[c * POS + i0] * (1.f - w) + src[c * POS + i1] * w;
    }
}

// ---------------- tiled SGEMM common config ----------------
#define TM 128
#define TN 128
#define TK 16

// shared inner-product body (f32x2 packed)
#define MICRO_KLOOP(As, Bs, ry, cx, acc2)                                    \
    _Pragma("unroll")                                                        \
    for (int kk = 0; kk < TK; kk++) {                                        \
        float a_s[8];                                                        \
        *(float4*)(a_s)     = *(const float4*)&As[kk][ry];                   \
        *(float4*)(a_s + 4) = *(const float4*)&As[kk][ry + 4];               \
        ulonglong2 b01 = *(const ulonglong2*)&Bs[kk][cx];                    \
        ulonglong2 b23 = *(const ulonglong2*)&Bs[kk][cx + 4];                \
        unsigned long long br2[4] = {b01.x, b01.y, b23.x, b23.y};            \
        _Pragma("unroll")                                                    \
        for (int i = 0; i < 8; i++) {                                        \
            unsigned long long a2 = dup2(a_s[i]);                            \
            ffma2(acc2[i][0], a2, br2[0]);                                   \
            ffma2(acc2[i][1], a2, br2[1]);                                   \
            ffma2(acc2[i][2], a2, br2[2]);                                   \
            ffma2(acc2[i][3], a2, br2[3]);                                   \
        }                                                                    \
    }

// GEMM 1: y[b] (512 x 4096) = Wall @ x[b] + bias
__global__ void __launch_bounds__(256, 2)
k_gemm_qkv(const float* __restrict__ X,
           const float* __restrict__ bq, const float* __restrict__ bkk,
           const float* __restrict__ bvv)
{
    int b  = blockIdx.z;
    int m0 = blockIdx.y * TM;
    int n0 = blockIdx.x * TN;
    __shared__ float As[TK][TM];
    __shared__ float Bs[TK][TN];
    int t  = threadIdx.x;
    int ty = t >> 4, tx = t & 15;
    int ry = ty * 8, cx = tx * 8;
    unsigned long long acc2[8][4];
#pragma unroll
    for (int i = 0; i < 8; i++)
#pragma unroll
        for (int j = 0; j < 4; j++) acc2[i][j] = 0ull;

    const float* Xb = X + b * (CDIM * NPIX);
    for (int k0 = 0; k0 < CDIM; k0 += TK) {
#pragma unroll
        for (int l = 0; l < 2; l++) {
            int v = t + l * 256;
            int am = v >> 2, ak = (v & 3) * 4;
            float4 a4 = *(const float4*)(g_Wall + (m0 + am) * CDIM + k0 + ak);
            As[ak + 0][am] = a4.x; As[ak + 1][am] = a4.y;
            As[ak + 2][am] = a4.z; As[ak + 3][am] = a4.w;
            int bkr = v >> 5, bnc = (v & 31) * 4;
            *(float4*)&Bs[bkr][bnc] = *(const float4*)(Xb + (k0 + bkr) * NPIX + n0 + bnc);
        }
        __syncthreads();
        MICRO_KLOOP(As, Bs, ry, cx, acc2)
        __syncthreads();
    }
#pragma unroll
    for (int i = 0; i < 8; i++) {
        int oc = m0 + ry + i;
        float bias = (oc < 128) ? bq[oc] : (oc < 256) ? bkk[oc - 128] : bvv[oc - 256];
        float* orow = d_y + (b * CQKV + oc) * NPIX + n0 + cx;
#pragma unroll
        for (int j = 0; j < 4; j++) {
            float2 p = unpk(acc2[i][j]);
            orow[2 * j + 0] = p.x + bias;
            orow[2 * j + 1] = p.y + bias;
        }
    }
}

// means over W (rowmean) and H (colmean) of y
__global__ void k_means()
{
    int c = blockIdx.x, b = blockIdx.y;
    __shared__ float buf[64][65];
    const float* row = d_y + (b * CQKV + c) * NPIX;
    int t = threadIdx.x;
#pragma unroll
    for (int l = 0; l < 16; l++) {
        int p = t + l * 256;
        buf[p >> 6][p & 63] = row[p];
    }
    __syncthreads();
    if (t < 64) {
        float s = 0.f;
#pragma unroll
        for (int w = 0; w < 64; w++) s += buf[t][w];
        d_rowmean[(b * CQKV + c) * 64 + t] = s * (1.f / 64.f);
    } else if (t < 128) {
        int w = t - 64;
        float s = 0.f;
#pragma unroll
        for (int h = 0; h < 64; h++) s += buf[h][w];
        d_colmean[(b * CQKV + c) * 64 + w] = s * (1.f / 64.f);
    }
}

// tiny axial attention: one block per (head, batch, dir); 64 threads (one per position)
__global__ void k_attn()
{
    int head = blockIdx.x, b = blockIdx.y, dir = blockIdx.z;
    const float* mean = dir ? d_colmean : d_rowmean;
    const float* peq  = g_pe + (dir ? 2 : 0) * (NHKD * 64);
    const float* pek  = g_pe + (dir ? 3 : 1) * (NHKD * 64);
    float* outp = dir ? d_attC : d_attR;
    __shared__ float km[KD][64];
    __shared__ float vm[DHEAD][64];
    int t = threadIdx.x;  // 0..63
#pragma unroll
    for (int l = 0; l < KD; l++) {
        int idx = t + l * 64;
        int kd = idx >> 6, i = idx & 63;
        int c = head * KD + kd;
        km[kd][i] = mean[(b * CQKV + c) * 64 + i] + pek[c * 64 + i];
    }
#pragma unroll
    for (int l = 0; l < DHEAD; l++) {
        int idx = t + l * 64;
        int d = idx >> 6, i = idx & 63;
        int c = DH + head * DHEAD + d;   // v starts at channel 256
        vm[d][i] = mean[(b * CQKV + c) * 64 + i];
    }
    float qreg[KD];
#pragma unroll
    for (int kd = 0; kd < KD; kd++) {
        int c = head * KD + kd;
        qreg[kd] = mean[(b * CQKV + c) * 64 + t] + peq[c * 64 + t];
    }
    __syncthreads();
    float lg[64];
    float mx = -1e30f;
#pragma unroll
    for (int j = 0; j < 64; j++) {
        float s = 0.f;
#pragma unroll
        for (int kd = 0; kd < KD; kd++) s += qreg[kd] * km[kd][j];
        s *= 0.25f;   // KEY_DIM^-0.5
        lg[j] = s;
        mx = fmaxf(mx, s);
    }
    float sum = 0.f;
#pragma unroll
    for (int j = 0; j < 64; j++) {
        float e = __expf(lg[j] - mx);
        lg[j] = e;
        sum += e;
    }
    float inv = 1.f / sum;
    for (int d = 0; d < DHEAD; d++) {
        float o = 0.f;
#pragma unroll
        for (int j = 0; j < 64; j++) o += lg[j] * vm[d][j];
        o *= inv;
        outp[(b * DH + head * DHEAD + d) * 64 + t] = fmaxf(o, 0.f);   // relu before conv
    }
}

// xr = Wr' @ attR + br ; xc = Wc' @ attC + bc   (tiny: 256x64 per batch-dir)
__global__ void k_xconv(const float* __restrict__ br, const float* __restrict__ bc)
{
    int dir = blockIdx.z, b = blockIdx.y;
    int idx = blockIdx.x * 256 + threadIdx.x;  // 0..16383
    int oc = idx >> 6, pos = idx & 63;
    const float* W = dir ? g_Wc : g_Wr;
    const float* a = (dir ? d_attC : d_attR) + b * DH * 64;
    float acc = 0.f;
#pragma unroll 8
    for (int k = 0; k < DH; k++) acc += W[oc * DH + k] * a[k * 64 + pos];
    float bias = dir ? bc[oc] : br[oc];
    float* o = (dir ? d_xc : d_xr);
    o[(b * DH + oc) * 64 + pos] = acc + bias;
}

// GEMM 2: gate[b] (256 x 4096) = Wpw' @ relu(gdw*y + bdw) + bpw
__global__ void __launch_bounds__(256, 2)
k_gate(const float* __restrict__ bdw, const float* __restrict__ bpw)
{
    int b  = blockIdx.z;
    int m0 = blockIdx.y * TM;
    int n0 = blockIdx.x * TN;
    __shared__ float As[TK][TM];
    __shared__ float Bs[TK][TN];
    int t  = threadIdx.x;
    int ty = t >> 4, tx = t & 15;
    int ry = ty * 8, cx = tx * 8;
    unsigned long long acc2[8][4];
#pragma unroll
    for (int i = 0; i < 8; i++)
#pragma unroll
        for (int j = 0; j < 4; j++) acc2[i][j] = 0ull;

    for (int k0 = 0; k0 < CQKV; k0 += TK) {
#pragma unroll
        for (int l = 0; l < 2; l++) {
            int v = t + l * 256;
            int am = v >> 2, ak = (v & 3) * 4;
            float4 a4 = *(const float4*)(g_Wpw + (m0 + am) * CQKV + k0 + ak);
            As[ak + 0][am] = a4.x; As[ak + 1][am] = a4.y;
            As[ak + 2][am] = a4.z; As[ak + 3][am] = a4.w;
            int bkr = v >> 5, bnc = (v & 31) * 4;
            int c = k0 + bkr;
            float g = g_gdw[c], bb = bdw[c];
            float4 yv = *(const float4*)(d_y + (b * CQKV + c) * NPIX + n0 + bnc);
            yv.x = fmaxf(fmaf(yv.x, g, bb), 0.f);
            yv.y = fmaxf(fmaf(yv.y, g, bb), 0.f);
            yv.z = fmaxf(fmaf(yv.z, g, bb), 0.f);
            yv.w = fmaxf(fmaf(yv.w, g, bb), 0.f);
            *(float4*)&Bs[bkr][bnc] = yv;
        }
        __syncthreads();
        MICRO_KLOOP(As, Bs, ry, cx, acc2)
        __syncthreads();
    }
#pragma unroll
    for (int i = 0; i < 8; i++) {
        int oc = m0 + ry + i;
        float bias = bpw[oc];
        float* orow = d_gate + (b * CDIM + oc) * NPIX + n0 + cx;
#pragma unroll
        for (int j = 0; j < 4; j++) {
            float2 p = unpk(acc2[i][j]);
            orow[2 * j + 0] = p.x + bias;
            orow[2 * j + 1] = p.y + bias;
        }
    }
}

// GEMM 3 + epilogue: out = hsig(Wp' @ relu(v + xr + xc) + bp) * gate
__global__ void __launch_bounds__(256, 2)
k_final(const float* __restrict__ bp, float* __restrict__ out)
{
    int b  = blockIdx.z;
    int m0 = blockIdx.y * TM;
    int n0 = blockIdx.x * TN;
    __shared__ float As[TK][TM];
    __shared__ float Bs[TK][TN];
    int t  = threadIdx.x;
    int ty = t >> 4, tx = t & 15;
    int ry = ty * 8, cx = tx * 8;
    unsigned long long acc2[8][4];
#pragma unroll
    for (int i = 0; i < 8; i++)
#pragma unroll
        for (int j = 0; j < 4; j++) acc2[i][j] = 0ull;

    for (int k0 = 0; k0 < DH; k0 += TK) {
#pragma unroll
        for (int l = 0; l < 2; l++) {
            int v = t + l * 256;
            int am = v >> 2, ak = (v & 3) * 4;
            float4 a4 = *(const float4*)(g_Wp + (m0 + am) * DH + k0 + ak);
            As[ak + 0][am] = a4.x; As[ak + 1][am] = a4.y;
            As[ak + 2][am] = a4.z; As[ak + 3][am] = a4.w;
            int bkr = v >> 5, bnc = (v & 31) * 4;
            int c = k0 + bkr;
            int p = n0 + bnc;
            int h = p >> 6, wb = p & 63;
            float4 yv = *(const float4*)(d_y + (b * CQKV + DH + c) * NPIX + p);
            float xrv = d_xr[(b * DH + c) * 64 + h];
            const float* xcr = d_xc + (b * DH + c) * 64;
            yv.x = fmaxf(yv.x + xrv + xcr[wb + 0], 0.f);
            yv.y = fmaxf(yv.y + xrv + xcr[wb + 1], 0.f);
            yv.z = fmaxf(yv.z + xrv + xcr[wb + 2], 0.f);
            yv.w = fmaxf(yv.w + xrv + xcr[wb + 3], 0.f);
            *(float4*)&Bs[bkr][bnc] = yv;
        }
        __syncthreads();
        MICRO_KLOOP(As, Bs, ry, cx, acc2)
        __syncthreads();
    }
#pragma unroll
    for (int i = 0; i < 8; i++) {
        int oc = m0 + ry + i;
        float bias = bp[oc];
        const float* grow = d_gate + (b * CDIM + oc) * NPIX + n0 + cx;
        float* orow = out + (b * CDIM + oc) * NPIX + n0 + cx;
#pragma unroll
        for (int j = 0; j < 4; j++) {
            float2 p = unpk(acc2[i][j]);
            float t0 = p.x + bias;
            float t1 = p.y + bias;
            float h0 = fminf(fmaxf(t0 + 3.f, 0.f), 6.f) * (1.f / 6.f);
            float h1 = fminf(fmaxf(t1 + 3.f, 0.f), 6.f) * (1.f / 6.f);
            orow[2 * j + 0] = h0 * grow[2 * j + 0];
            orow[2 * j + 1] = h1 * grow[2 * j + 1];
        }
    }
}

// ---------------- launch ----------------
extern "C" void kernel_launch(void* const* d_in, const int* in_sizes, int n_in,
                              void* d_out, int out_size)
{
    const float* x     = (const float*)d_in[0];
    const float* Wq    = (const float*)d_in[1];
    const float* sq    = (const float*)d_in[2];
    const float* bq    = (const float*)d_in[3];
    const float* Wk    = (const float*)d_in[4];
    const float* sk    = (const float*)d_in[5];
    const float* bk    = (const float*)d_in[6];
    const float* Wv    = (const float*)d_in[7];
    const float* sv    = (const float*)d_in[8];
    const float* bv    = (const float*)d_in[9];
    const float* pe_rq = (const float*)d_in[10];
    const float* pe_rk = (const float*)d_in[11];
    const float* pe_cq = (const float*)d_in[12];
    const float* pe_ck = (const float*)d_in[13];
    const float* wdw   = (const float*)d_in[14];
    const float* sdw   = (const float*)d_in[15];
    const float* bdw   = (const float*)d_in[16];
    const float* Wpw   = (const float*)d_in[17];
    const float* spw   = (const float*)d_in[18];
    const float* bpw   = (const float*)d_in[19];
    const float* Wr    = (const float*)d_in[20];
    const float* sr    = (const float*)d_in[21];
    const float* br    = (const float*)d_in[22];
    const float* Wc    = (const float*)d_in[23];
    const float* sc    = (const float*)d_in[24];
    const float* bc    = (const float*)d_in[25];
    const float* Wp    = (const float*)d_in[26];
    const float* sp    = (const float*)d_in[27];
    const float* bp    = (const float*)d_in[28];
    float* out = (float*)d_out;

    k_prep<<<512, 256>>>(Wq, sq, Wk, sk, Wv, sv, Wpw, spw, Wp, sp,
                         Wr, sr, Wc, sc, wdw, sdw, pe_rq, pe_rk, pe_cq, pe_ck);
    k_gemm_qkv<<<dim3(NPIX / TN, CQKV / TM, NB), 256>>>(x, bq, bk, bv);
    k_means<<<dim3(CQKV, NB), 256>>>();
    k_attn<<<dim3(HEADS, NB, 2), 64>>>();
    k_xconv<<<dim3(64, NB, 2), 256>>>(br, bc);
    k_gate<<<dim3(NPIX / TN, CDIM / TM, NB), 256>>>(bdw, bpw);
    k_final<<<dim3(NPIX / TN, CDIM / TM, NB), 256>>>(bp, out);
}